// round 4
// baseline (speedup 1.0000x reference)
#include <cuda_runtime.h>
#include <cuda_bf16.h>

#define T_TOK   8192
#define DMODEL  1024
#define NEXP    8
#define DFF     4096
#define CAP     1280   // int(1.25 * 8192 / 8)

typedef unsigned int u32;
typedef unsigned long long u64;

// ---------------- scratch (device globals; no allocation) ----------------
__device__ __nv_bfloat16 g_a_hi [(size_t)NEXP * CAP * DMODEL];
__device__ __nv_bfloat16 g_a_lo [(size_t)NEXP * CAP * DMODEL];
__device__ __nv_bfloat16 g_w1t_hi[(size_t)NEXP * DFF * DMODEL];
__device__ __nv_bfloat16 g_w1t_lo[(size_t)NEXP * DFF * DMODEL];
__device__ __nv_bfloat16 g_w2t_hi[(size_t)NEXP * DMODEL * DFF];
__device__ __nv_bfloat16 g_w2t_lo[(size_t)NEXP * DMODEL * DFF];
__device__ __nv_bfloat16 g_h_hi [(size_t)NEXP * CAP * DFF];
__device__ __nv_bfloat16 g_h_lo [(size_t)NEXP * CAP * DFF];
__device__ float         g_eo   [(size_t)NEXP * CAP * DMODEL];
__device__ int   g_idx [T_TOK];
__device__ float g_gate[T_TOK];
__device__ int   g_slot[T_TOK];

// ---------------- PTX helpers (plain sm_103-legal: sm_80/sm_90 features only) ----------------
__device__ __forceinline__ u32 smem_u32(const void* p) {
    u32 a; asm("{ .reg .u64 t; cvta.to.shared.u64 t, %1; cvt.u32.u64 %0, t; }" : "=r"(a) : "l"(p));
    return a;
}
__device__ __forceinline__ void cpa16(u32 s, const void* g) {
    asm volatile("cp.async.cg.shared.global [%0], [%1], 16;" :: "r"(s), "l"(g));
}
__device__ __forceinline__ void cpa_commit() { asm volatile("cp.async.commit_group;" ::: "memory"); }
__device__ __forceinline__ void cpa_wait1()  { asm volatile("cp.async.wait_group 1;" ::: "memory"); }
__device__ __forceinline__ void cpa_wait0()  { asm volatile("cp.async.wait_group 0;" ::: "memory"); }

__device__ __forceinline__ void ldsm4(u32* r, u32 addr) {
    asm volatile("ldmatrix.sync.aligned.m8n8.x4.shared.b16 {%0,%1,%2,%3}, [%4];"
                 : "=r"(r[0]), "=r"(r[1]), "=r"(r[2]), "=r"(r[3]) : "r"(addr));
}
__device__ __forceinline__ void mma16816(float* d, const u32* a, u32 b0, u32 b1) {
    asm volatile(
        "mma.sync.aligned.m16n8k16.row.col.f32.bf16.bf16.f32 "
        "{%0,%1,%2,%3},{%4,%5,%6,%7},{%8,%9},{%0,%1,%2,%3};"
        : "+f"(d[0]), "+f"(d[1]), "+f"(d[2]), "+f"(d[3])
        : "r"(a[0]), "r"(a[1]), "r"(a[2]), "r"(a[3]), "r"(b0), "r"(b1));
}

__device__ __forceinline__ void split_bf16(float v, __nv_bfloat16& h, __nv_bfloat16& l) {
    h = __float2bfloat16(v);
    l = __float2bfloat16(v - __bfloat162float(h));
}

// ---------------- 1. gating ----------------
__global__ void gate_kernel(const float* __restrict__ x, const float* __restrict__ wg) {
    __shared__ float wgT[NEXP][DMODEL];
    int tid = threadIdx.x;
    for (int i = tid; i < DMODEL * NEXP; i += 256)
        wgT[i & 7][i >> 3] = wg[i];
    __syncthreads();
    int warp = tid >> 5, lane = tid & 31;
    int t = blockIdx.x * 8 + warp;
    const float* xr = x + (size_t)t * DMODEL;
    float acc[NEXP];
#pragma unroll
    for (int e = 0; e < NEXP; e++) acc[e] = 0.0f;
    for (int m = lane; m < DMODEL; m += 32) {
        float xv = xr[m];
#pragma unroll
        for (int e = 0; e < NEXP; e++) acc[e] += xv * wgT[e][m];
    }
#pragma unroll
    for (int e = 0; e < NEXP; e++)
#pragma unroll
        for (int o = 16; o; o >>= 1)
            acc[e] += __shfl_xor_sync(0xffffffffu, acc[e], o);
    if (lane == 0) {
        float mx = acc[0]; int a = 0;
#pragma unroll
        for (int e = 1; e < NEXP; e++)
            if (acc[e] > mx) { mx = acc[e]; a = e; }   // first-max, matches jnp.argmax
        float s = 0.0f;
#pragma unroll
        for (int e = 0; e < NEXP; e++) s += expf(acc[e] - mx);
        g_idx[t]  = a;
        g_gate[t] = 1.0f / s;
    }
}

// ---------------- 2. queue positions (warp-scan, 256 threads x 32 tokens) ----------------
__global__ void scan_kernel() {
    __shared__ int wsum[8][NEXP];
    __shared__ int wbase[8][NEXP];
    int tid = threadIdx.x, wid = tid >> 5, lane = tid & 31;
    int loc[32];
    int cnt[NEXP];
#pragma unroll
    for (int e = 0; e < NEXP; e++) cnt[e] = 0;
#pragma unroll
    for (int j = 0; j < 32; j++) {
        loc[j] = g_idx[tid * 32 + j];
        cnt[loc[j]]++;
    }
    int excl[NEXP];
#pragma unroll
    for (int e = 0; e < NEXP; e++) {
        int inc = cnt[e];
#pragma unroll
        for (int off = 1; off < 32; off <<= 1) {
            int n = __shfl_up_sync(0xffffffffu, inc, off);
            if (lane >= off) inc += n;
        }
        excl[e] = inc - cnt[e];
        if (lane == 31) wsum[wid][e] = inc;
    }
    __syncthreads();
    if (tid == 0) {
#pragma unroll
        for (int e = 0; e < NEXP; e++) {
            int run = 0;
            for (int w = 0; w < 8; w++) { wbase[w][e] = run; run += wsum[w][e]; }
        }
    }
    __syncthreads();
    int pos[NEXP];
#pragma unroll
    for (int e = 0; e < NEXP; e++) pos[e] = wbase[wid][e] + excl[e];
#pragma unroll
    for (int j = 0; j < 32; j++) {
        int e = loc[j];
        int p = pos[e]++;
        g_slot[tid * 32 + j] = (p < CAP) ? p : -1;
    }
}

// ---------------- 3. dispatch: gather + bf16 hi/lo split ----------------
__global__ void gather_kernel(const float* __restrict__ x) {
    int t = blockIdx.x;
    int sl = g_slot[t];
    if (sl < 0) return;
    int e = g_idx[t];
    int i = threadIdx.x;                       // 256 threads x 4 floats
    float4 v = ((const float4*)(x + (size_t)t * DMODEL))[i];
    __nv_bfloat16 h0, l0, h1, l1, h2, l2, h3, l3;
    split_bf16(v.x, h0, l0); split_bf16(v.y, h1, l1);
    split_bf16(v.z, h2, l2); split_bf16(v.w, h3, l3);
    size_t base = ((size_t)e * CAP + sl) * DMODEL + i * 4;
    uint2 ph = make_uint2((u32)__bfloat16_as_ushort(h0) | ((u32)__bfloat16_as_ushort(h1) << 16),
                          (u32)__bfloat16_as_ushort(h2) | ((u32)__bfloat16_as_ushort(h3) << 16));
    uint2 pl = make_uint2((u32)__bfloat16_as_ushort(l0) | ((u32)__bfloat16_as_ushort(l1) << 16),
                          (u32)__bfloat16_as_ushort(l2) | ((u32)__bfloat16_as_ushort(l3) << 16));
    *(uint2*)(g_a_hi + base) = ph;
    *(uint2*)(g_a_lo + base) = pl;
}

// ---------------- weight transpose + split: src[e][R][C] -> dst[e][C][R] ----------------
__global__ void transpose_split_kernel(const float* __restrict__ src,
                                       __nv_bfloat16* __restrict__ dhi,
                                       __nv_bfloat16* __restrict__ dlo,
                                       int R, int C) {
    __shared__ float tile[32][33];
    int e = blockIdx.z;
    src += (size_t)e * R * C;
    size_t ob = (size_t)e * R * C;
    int c0 = blockIdx.x * 32, r0 = blockIdx.y * 32;
    int tx = threadIdx.x, ty = threadIdx.y;
#pragma unroll
    for (int j = 0; j < 32; j += 8)
        tile[ty + j][tx] = src[(size_t)(r0 + ty + j) * C + c0 + tx];
    __syncthreads();
#pragma unroll
    for (int j = 0; j < 32; j += 8) {
        float v = tile[tx][ty + j];
        __nv_bfloat16 h, l;
        split_bf16(v, h, l);
        size_t idx = ob + (size_t)(c0 + ty + j) * R + r0 + tx;
        dhi[idx] = h;
        dlo[idx] = l;
    }
}

// ---------------- 4. bf16-split HMMA GEMM (mma.sync m16n8k16) ----------------
// C tile 128x128, BK=32 bf16, 8 warps (2x4), warp tile 64x32.
// D = Ahi*Bhi^T + Ahi*Blo^T + Alo*Bhi^T   (fp32 accumulate in registers)
// SMEM stage: 4 sub-tiles (Ahi, Alo, Bhi, Blo), each 128 rows x 32 bf16,
// padded row stride 80B (conflict-free ldmatrix: 80k mod 128 covers all 16B banks).
#define ROWB      80
#define TILE_B    (128 * ROWB)       // 10240
#define STAGE_B   (4 * TILE_B)       // 40960
#define GEMM_SMEM (2 * STAGE_B)      // 81920

template<int KTOT, int NFULL, int PHASE>
__global__ __launch_bounds__(256, 1)
void moe_gemm(const __nv_bfloat16* __restrict__ Bhi,
              const __nv_bfloat16* __restrict__ Blo,
              const float* __restrict__ bias) {
    extern __shared__ char smem[];
    constexpr int NCH = KTOT / 32;
    const int e = blockIdx.z;
    const int bm = blockIdx.y * 128;
    const int bn = blockIdx.x * 128;
    const int tid = threadIdx.x, wid = tid >> 5, lane = tid & 31;
    const int wm = (wid >> 2) * 64;      // warp row offset in tile
    const int wn = (wid & 3) * 32;       // warp col offset in tile

    const __nv_bfloat16* Ahi = ((PHASE == 1) ? g_a_hi : g_h_hi) + (size_t)e * CAP * KTOT;
    const __nv_bfloat16* Alo = ((PHASE == 1) ? g_a_lo : g_h_lo) + (size_t)e * CAP * KTOT;
    Bhi  += (size_t)e * NFULL * KTOT;
    Blo  += (size_t)e * NFULL * KTOT;
    bias += (size_t)e * NFULL;

    const u32 sbase = smem_u32(smem);

    // async stage loader: 2048 x 16B chunks per stage (4 tiles x 128 rows x 4 segs)
    auto load_chunk = [&](int c) {
        u32 st = sbase + (u32)(c & 1) * STAGE_B;
        int koff = c * 32;
#pragma unroll
        for (int u = 0; u < 8; u++) {
            int cid = tid + u * 256;
            int tile = cid >> 9;
            int rem = cid & 511;
            int row = rem >> 2;
            int seg = rem & 3;
            const __nv_bfloat16* gp;
            if      (tile == 0) gp = Ahi + (size_t)(bm + row) * KTOT + koff + seg * 8;
            else if (tile == 1) gp = Alo + (size_t)(bm + row) * KTOT + koff + seg * 8;
            else if (tile == 2) gp = Bhi + (size_t)(bn + row) * KTOT + koff + seg * 8;
            else                gp = Blo + (size_t)(bn + row) * KTOT + koff + seg * 8;
            cpa16(st + (u32)tile * TILE_B + (u32)row * ROWB + (u32)seg * 16, gp);
        }
        cpa_commit();
    };

    float acc[4][4][4];
#pragma unroll
    for (int i = 0; i < 4; i++)
#pragma unroll
        for (int j = 0; j < 4; j++)
#pragma unroll
            for (int q = 0; q < 4; q++) acc[i][j][q] = 0.0f;

    load_chunk(0);
    load_chunk(1);

    const int lrow = lane & 7, g = lane >> 3;
    const int a_r = ((g & 1) << 3) + lrow;   // A: m0=r0-7/k0-7, m1=r8-15/k0-7, m2=r0-7/k8-15, m3=r8-15/k8-15
    const int a_c = ((g >> 1) << 3);
    const int b_r = ((g >> 1) << 3) + lrow;  // B: m0=n0-7/k0-7, m1=n0-7/k8-15, m2=n8-15/k0-7, m3=n8-15/k8-15
    const int b_c = ((g & 1) << 3);

    for (int c = 0; c < NCH; c++) {
        if (c + 1 < NCH) cpa_wait1(); else cpa_wait0();
        __syncthreads();
        u32 st = sbase + (u32)(c & 1) * STAGE_B;
#pragma unroll
        for (int kk = 0; kk < 32; kk += 16) {
            u32 ahi[4][4], alo[4][4];
#pragma unroll
            for (int i = 0; i < 4; i++) {
                u32 ad = st + (u32)(wm + i * 16 + a_r) * ROWB + (u32)(kk + a_c) * 2;
                ldsm4(ahi[i], ad);
                ldsm4(alo[i], ad + TILE_B);
            }
            u32 bh[2][4], bl[2][4];
#pragma unroll
            for (int j2 = 0; j2 < 2; j2++) {
                u32 bd = st + 2 * TILE_B + (u32)(wn + j2 * 16 + b_r) * ROWB + (u32)(kk + b_c) * 2;
                ldsm4(bh[j2], bd);
                ldsm4(bl[j2], bd + TILE_B);
            }
#pragma unroll
            for (int i = 0; i < 4; i++)
#pragma unroll
                for (int j = 0; j < 4; j++) {
                    u32 h0 = bh[j >> 1][(j & 1) * 2], h1 = bh[j >> 1][(j & 1) * 2 + 1];
                    u32 l0 = bl[j >> 1][(j & 1) * 2], l1 = bl[j >> 1][(j & 1) * 2 + 1];
                    mma16816(acc[i][j], ahi[i], h0, h1);
                    mma16816(acc[i][j], ahi[i], l0, l1);
                    mma16816(acc[i][j], alo[i], h0, h1);
                }
        }
        if (c + 2 < NCH) {
            __syncthreads();          // all warps done reading stage (c&1) before overwrite
            load_chunk(c + 2);
        }
    }

    // ---------------- epilogue ----------------
    const int gr = lane >> 2;            // row within 16-row frag (0-7; +8 for c2,c3)
    const int gc = (lane & 3) * 2;       // col within 8-col frag
#pragma unroll
    for (int i = 0; i < 4; i++) {
        int row0 = bm + wm + i * 16 + gr;
#pragma unroll
        for (int j = 0; j < 4; j++) {
            int col = bn + wn + j * 8 + gc;
            float bv0 = bias[col], bv1 = bias[col + 1];
#pragma unroll
            for (int half = 0; half < 2; half++) {
                int row = row0 + half * 8;
                float v0 = acc[i][j][half * 2]     + bv0;
                float v1 = acc[i][j][half * 2 + 1] + bv1;
                if (PHASE == 1) {
                    v0 = fmaxf(v0, 0.0f);
                    v1 = fmaxf(v1, 0.0f);
                    __nv_bfloat16 h0, l0, h1, l1;
                    split_bf16(v0, h0, l0);
                    split_bf16(v1, h1, l1);
                    size_t o = ((size_t)e * CAP + row) * NFULL + col;
                    *(u32*)(g_h_hi + o) = (u32)__bfloat16_as_ushort(h0) | ((u32)__bfloat16_as_ushort(h1) << 16);
                    *(u32*)(g_h_lo + o) = (u32)__bfloat16_as_ushort(l0) | ((u32)__bfloat16_as_ushort(l1) << 16);
                } else {
                    size_t o = ((size_t)e * CAP + row) * NFULL + col;
                    *(float2*)(g_eo + o) = make_float2(v0, v1);
                }
            }
        }
    }
}

// ---------------- 5. combine ----------------
__global__ void combine_kernel(float* __restrict__ out) {
    int t = blockIdx.x;
    int sl = g_slot[t];
    float4* o = (float4*)(out + (size_t)t * DMODEL);
    int i = threadIdx.x;
    if (sl < 0) {
        o[i] = make_float4(0.f, 0.f, 0.f, 0.f);
        return;
    }
    float g = g_gate[t];
    int e = g_idx[t];
    float4 v = ((const float4*)(g_eo + ((size_t)e * CAP + sl) * DMODEL))[i];
    o[i] = make_float4(v.x * g, v.y * g, v.z * g, v.w * g);
}

// ---------------- launch ----------------
extern "C" void kernel_launch(void* const* d_in, const int* in_sizes, int n_in,
                              void* d_out, int out_size) {
    const float* x  = (const float*)d_in[0];   // [4,2048,1024]
    const float* wg = (const float*)d_in[1];   // [1024,8]
    const float* w1 = (const float*)d_in[2];   // [8,1024,4096]
    const float* b1 = (const float*)d_in[3];   // [8,4096]
    const float* w2 = (const float*)d_in[4];   // [8,4096,1024]
    const float* b2 = (const float*)d_in[5];   // [8,1024]
    float* out = (float*)d_out;                // [4,2048,1024]

    cudaFuncSetAttribute(moe_gemm<DMODEL, DFF, 1>,
                         cudaFuncAttributeMaxDynamicSharedMemorySize, GEMM_SMEM);
    cudaFuncSetAttribute(moe_gemm<DFF, DMODEL, 2>,
                         cudaFuncAttributeMaxDynamicSharedMemorySize, GEMM_SMEM);

    // weight prep: w1 [e][1024][4096] -> w1t [e][4096][1024]; w2 [e][4096][1024] -> w2t [e][1024][4096]
    transpose_split_kernel<<<dim3(DFF / 32, DMODEL / 32, NEXP), dim3(32, 8)>>>(w1, g_w1t_hi, g_w1t_lo, DMODEL, DFF);
    transpose_split_kernel<<<dim3(DMODEL / 32, DFF / 32, NEXP), dim3(32, 8)>>>(w2, g_w2t_hi, g_w2t_lo, DFF, DMODEL);

    gate_kernel<<<T_TOK / 8, 256>>>(x, wg);
    scan_kernel<<<1, 256>>>();
    gather_kernel<<<T_TOK, 256>>>(x);

    moe_gemm<DMODEL, DFF, 1><<<dim3(DFF / 128, CAP / 128, NEXP), 256, GEMM_SMEM>>>(g_w1t_hi, g_w1t_lo, b1);
    moe_gemm<DFF, DMODEL, 2><<<dim3(DMODEL / 128, CAP / 128, NEXP), 256, GEMM_SMEM>>>(g_w2t_hi, g_w2t_lo, b2);

    combine_kernel<<<T_TOK, 256>>>(out);
}

// round 5
// speedup vs baseline: 7.3230x; 7.3230x over previous
#include <cuda_runtime.h>

#define T_TOK   8192
#define DMODEL  1024
#define NEXP    8
#define DFF     4096
#define CAP     1280   // int(1.25 * 8192 / 8)

typedef unsigned int u32;
typedef unsigned long long ull;

// ---------------- scratch (device globals; no allocation) ----------------
__device__ float g_disp[(size_t)NEXP * CAP * DMODEL];   // 40 MB
__device__ float g_h   [(size_t)NEXP * CAP * DFF];      // 167 MB
__device__ float g_eo  [(size_t)NEXP * CAP * DMODEL];   // 40 MB
__device__ int   g_idx [T_TOK];
__device__ float g_gate[T_TOK];
__device__ int   g_slot[T_TOK];

// ---------------- packed f32x2 + async-copy helpers ----------------
__device__ __forceinline__ ull pk(float x, float y) {
    ull r; asm("mov.b64 %0, {%1, %2};" : "=l"(r) : "f"(x), "f"(y)); return r;
}
__device__ __forceinline__ void upk(ull v, float& x, float& y) {
    asm("mov.b64 {%0, %1}, %2;" : "=f"(x), "=f"(y) : "l"(v));
}
__device__ __forceinline__ ull ffma2(ull a, ull b, ull c) {
    ull d; asm("fma.rn.f32x2 %0, %1, %2, %3;" : "=l"(d) : "l"(a), "l"(b), "l"(c)); return d;
}
__device__ __forceinline__ u32 smem_u32(const void* p) {
    u32 a; asm("{ .reg .u64 t; cvta.to.shared.u64 t, %1; cvt.u32.u64 %0, t; }" : "=r"(a) : "l"(p));
    return a;
}
__device__ __forceinline__ void cpa16(u32 s, const void* g) {
    asm volatile("cp.async.cg.shared.global [%0], [%1], 16;" :: "r"(s), "l"(g));
}
__device__ __forceinline__ void cpa_commit() { asm volatile("cp.async.commit_group;" ::: "memory"); }
__device__ __forceinline__ void cpa_wait1()  { asm volatile("cp.async.wait_group 1;" ::: "memory"); }
__device__ __forceinline__ void cpa_wait0()  { asm volatile("cp.async.wait_group 0;" ::: "memory"); }

// ---------------- 1. gating ----------------
__global__ void gate_kernel(const float* __restrict__ x, const float* __restrict__ wg) {
    __shared__ float wgT[NEXP][DMODEL];
    int tid = threadIdx.x;
    for (int i = tid; i < DMODEL * NEXP; i += 256)
        wgT[i & 7][i >> 3] = wg[i];
    __syncthreads();
    int warp = tid >> 5, lane = tid & 31;
    int t = blockIdx.x * 8 + warp;
    const float* xr = x + (size_t)t * DMODEL;
    float acc[NEXP];
#pragma unroll
    for (int e = 0; e < NEXP; e++) acc[e] = 0.0f;
    for (int m = lane; m < DMODEL; m += 32) {
        float xv = xr[m];
#pragma unroll
        for (int e = 0; e < NEXP; e++) acc[e] += xv * wgT[e][m];
    }
#pragma unroll
    for (int e = 0; e < NEXP; e++)
#pragma unroll
        for (int o = 16; o; o >>= 1)
            acc[e] += __shfl_xor_sync(0xffffffffu, acc[e], o);
    if (lane == 0) {
        float mx = acc[0]; int a = 0;
#pragma unroll
        for (int e = 1; e < NEXP; e++)
            if (acc[e] > mx) { mx = acc[e]; a = e; }   // first-max, matches jnp.argmax
        float s = 0.0f;
#pragma unroll
        for (int e = 0; e < NEXP; e++) s += expf(acc[e] - mx);
        g_idx[t]  = a;
        g_gate[t] = 1.0f / s;
    }
}

// ---------------- 2. queue positions (warp-scan, 256 threads x 32 tokens) ----------------
__global__ void scan_kernel() {
    __shared__ int wsum[8][NEXP];
    __shared__ int wbase[8][NEXP];
    int tid = threadIdx.x, wid = tid >> 5, lane = tid & 31;
    int loc[32];
    const int4* gp = (const int4*)(g_idx + tid * 32);
#pragma unroll
    for (int v = 0; v < 8; v++) {
        int4 q = gp[v];
        loc[v * 4 + 0] = q.x; loc[v * 4 + 1] = q.y;
        loc[v * 4 + 2] = q.z; loc[v * 4 + 3] = q.w;
    }
    int cnt[NEXP];
#pragma unroll
    for (int e = 0; e < NEXP; e++) cnt[e] = 0;
#pragma unroll
    for (int j = 0; j < 32; j++) cnt[loc[j]]++;
    int excl[NEXP];
#pragma unroll
    for (int e = 0; e < NEXP; e++) {
        int inc = cnt[e];
#pragma unroll
        for (int off = 1; off < 32; off <<= 1) {
            int n = __shfl_up_sync(0xffffffffu, inc, off);
            if (lane >= off) inc += n;
        }
        excl[e] = inc - cnt[e];
        if (lane == 31) wsum[wid][e] = inc;
    }
    __syncthreads();
    if (tid == 0) {
#pragma unroll
        for (int e = 0; e < NEXP; e++) {
            int run = 0;
            for (int w = 0; w < 8; w++) { wbase[w][e] = run; run += wsum[w][e]; }
        }
    }
    __syncthreads();
    int pos[NEXP];
#pragma unroll
    for (int e = 0; e < NEXP; e++) pos[e] = wbase[wid][e] + excl[e];
#pragma unroll
    for (int j = 0; j < 32; j++) {
        int e = loc[j];
        int p = pos[e]++;
        g_slot[tid * 32 + j] = (p < CAP) ? p : -1;
    }
}

// ---------------- 3. dispatch (gather tokens into [E,C,M]) ----------------
__global__ void gather_kernel(const float* __restrict__ x) {
    int t = blockIdx.x;
    int sl = g_slot[t];
    if (sl < 0) return;
    int e = g_idx[t];
    const float4* src = (const float4*)(x + (size_t)t * DMODEL);
    float4* dst = (float4*)(g_disp + ((size_t)e * CAP + sl) * DMODEL);
    dst[threadIdx.x] = src[threadIdx.x];   // 256 threads x float4
}

// ---------------- 4. per-expert SGEMM: cp.async pipelined, packed f32x2 FMA ----------------
// 128x128 tile, BK=16, 256 threads, 8x8 microtile, double-buffered stages.
// A [rows][K] row-major (register-prefetched, stored transposed to SMEM).
// B [K][N] row-major (cp.async direct into SMEM).
#define BK    16
#define PADW  132

template<int N, int K, bool RELU, int PHASE>
__global__ __launch_bounds__(256, 2)
void sgemm_kernel(const float* __restrict__ Bw, const float* __restrict__ biasb) {
    __shared__ float As[2][BK][PADW];
    __shared__ float Bs[2][BK][PADW];

    const int e = blockIdx.z;
    const float* A;
    float* Cc;
    if (PHASE == 1) {
        A  = g_disp + (size_t)e * CAP * DMODEL;
        Cc = g_h    + (size_t)e * CAP * DFF;
    } else {
        A  = g_h    + (size_t)e * CAP * DFF;
        Cc = g_eo   + (size_t)e * CAP * DMODEL;
    }
    const float* B    = Bw    + (size_t)e * K * N;
    const float* bias = biasb + (size_t)e * N;

    const int bm = blockIdx.y * 128;
    const int bn = blockIdx.x * 128;
    const int tid = threadIdx.x;
    const int ty = tid >> 4, tx = tid & 15;
    constexpr int NCH = K / BK;

    // A loader geometry: thread loads float4 j = tid*2+q : row j>>2, kq (j&3)*4
    const int ar  = tid >> 1;              // row 0..127
    const int ak0 = (tid & 1) * 8;         // kq of q=0 (q=1 -> +4)
    const float* Aptr = A + (size_t)(bm + ar) * K + ak0;

    // B loader geometry: chunk idx = tid*2+q : k = idx>>5, seg = idx&31
    const int bk0  = tid >> 4;             // k of q=0 chunk (idx even, idx>>5 = tid>>4)
    const int bseg = (tid * 2) & 31;       // seg of q=0 (q=1 -> +1)
    const float* Bptr = B + (size_t)bk0 * N + bn + bseg * 4;
    u32 bs_s0 = smem_u32(&Bs[0][bk0][bseg * 4]);
    u32 bs_s1 = smem_u32(&Bs[1][bk0][bseg * 4]);

    float4 areg[2][2];
    areg[0][0] = *(const float4*)(Aptr);
    areg[0][1] = *(const float4*)(Aptr + 4);
    cpa16(bs_s0,      Bptr);
    cpa16(bs_s0 + 16, Bptr + 4);
    cpa_commit();
    areg[1][0] = *(const float4*)(Aptr + BK);
    areg[1][1] = *(const float4*)(Aptr + BK + 4);
    cpa16(bs_s1,      Bptr + (size_t)BK * N);
    cpa16(bs_s1 + 16, Bptr + (size_t)BK * N + 4);
    cpa_commit();

    ull acc[8][4];
#pragma unroll
    for (int i = 0; i < 8; i++)
#pragma unroll
        for (int j = 0; j < 4; j++) acc[i][j] = 0ull;

#pragma unroll 1
    for (int c = 0; c < NCH; c++) {
        if (c + 1 < NCH) cpa_wait1(); else cpa_wait0();
        const int s = c & 1;
        // store this chunk's A fragment (held in regs) transposed into SMEM
#pragma unroll
        for (int q = 0; q < 2; q++) {
            float4 v = areg[s][q];
            int kq = ak0 + q * 4;
            As[s][kq + 0][ar] = v.x;
            As[s][kq + 1][ar] = v.y;
            As[s][kq + 2][ar] = v.z;
            As[s][kq + 3][ar] = v.w;
        }
        __syncthreads();
#pragma unroll
        for (int kk = 0; kk < BK; kk++) {
            float4 a0 = *(const float4*)&As[s][kk][ty * 8];
            float4 a1 = *(const float4*)&As[s][kk][ty * 8 + 4];
            float4 b0 = *(const float4*)&Bs[s][kk][tx * 8];
            float4 b1 = *(const float4*)&Bs[s][kk][tx * 8 + 4];
            ull bp0 = pk(b0.x, b0.y), bp1 = pk(b0.z, b0.w);
            ull bp2 = pk(b1.x, b1.y), bp3 = pk(b1.z, b1.w);
            float arr[8] = {a0.x, a0.y, a0.z, a0.w, a1.x, a1.y, a1.z, a1.w};
#pragma unroll
            for (int i = 0; i < 8; i++) {
                ull ap = pk(arr[i], arr[i]);
                acc[i][0] = ffma2(ap, bp0, acc[i][0]);
                acc[i][1] = ffma2(ap, bp1, acc[i][1]);
                acc[i][2] = ffma2(ap, bp2, acc[i][2]);
                acc[i][3] = ffma2(ap, bp3, acc[i][3]);
            }
        }
        __syncthreads();
        if (c + 2 < NCH) {
            const float* ap2 = Aptr + (size_t)(c + 2) * BK;
            areg[s][0] = *(const float4*)(ap2);
            areg[s][1] = *(const float4*)(ap2 + 4);
            const float* bp2g = Bptr + (size_t)(c + 2) * BK * N;
            u32 bss = s ? bs_s1 : bs_s0;
            cpa16(bss,      bp2g);
            cpa16(bss + 16, bp2g + 4);
            cpa_commit();
        }
    }

    // epilogue: bias (+relu) + store
    float bvals[8];
#pragma unroll
    for (int j = 0; j < 8; j++) bvals[j] = bias[bn + tx * 8 + j];
#pragma unroll
    for (int i = 0; i < 8; i++) {
        float o[8];
        upk(acc[i][0], o[0], o[1]);
        upk(acc[i][1], o[2], o[3]);
        upk(acc[i][2], o[4], o[5]);
        upk(acc[i][3], o[6], o[7]);
#pragma unroll
        for (int j = 0; j < 8; j++) {
            float v = o[j] + bvals[j];
            if (RELU) v = fmaxf(v, 0.0f);
            o[j] = v;
        }
        float* crow = Cc + (size_t)(bm + ty * 8 + i) * N + bn + tx * 8;
        *(float4*)crow       = make_float4(o[0], o[1], o[2], o[3]);
        *(float4*)(crow + 4) = make_float4(o[4], o[5], o[6], o[7]);
    }
}

// ---------------- 5. combine ----------------
__global__ void combine_kernel(float* __restrict__ out) {
    int t = blockIdx.x;
    int sl = g_slot[t];
    float4* o = (float4*)(out + (size_t)t * DMODEL);
    int i = threadIdx.x;
    if (sl < 0) {
        o[i] = make_float4(0.f, 0.f, 0.f, 0.f);   // dropped token -> zeros
        return;
    }
    float g = g_gate[t];
    int e = g_idx[t];
    float4 v = ((const float4*)(g_eo + ((size_t)e * CAP + sl) * DMODEL))[i];
    o[i] = make_float4(v.x * g, v.y * g, v.z * g, v.w * g);
}

// ---------------- launch ----------------
extern "C" void kernel_launch(void* const* d_in, const int* in_sizes, int n_in,
                              void* d_out, int out_size) {
    const float* x  = (const float*)d_in[0];   // [4,2048,1024]
    const float* wg = (const float*)d_in[1];   // [1024,8]
    const float* w1 = (const float*)d_in[2];   // [8,1024,4096]
    const float* b1 = (const float*)d_in[3];   // [8,4096]
    const float* w2 = (const float*)d_in[4];   // [8,4096,1024]
    const float* b2 = (const float*)d_in[5];   // [8,1024]
    float* out = (float*)d_out;                // [4,2048,1024]

    gate_kernel<<<T_TOK / 8, 256>>>(x, wg);
    scan_kernel<<<1, 256>>>();
    gather_kernel<<<T_TOK, 256>>>(x);
    sgemm_kernel<DFF, DMODEL, true, 1><<<dim3(DFF / 128, CAP / 128, NEXP), 256>>>(w1, b1);
    sgemm_kernel<DMODEL, DFF, false, 2><<<dim3(DMODEL / 128, CAP / 128, NEXP), 256>>>(w2, b2);
    combine_kernel<<<T_TOK, 256>>>(out);
}